// round 5
// baseline (speedup 1.0000x reference)
#include <cuda_runtime.h>

// APPNP, K=10:  g_{t+1} = 0.9*norm^2 * (sum_{(s->v) in E} g_t[s]) + 0.1*norm*feat0
// where g = norm ⊙ h. Final: h = 0.9*norm*agg + 0.1*feat0.
//
// CSR gather (edges counting-sorted by dst), zero atomics in the hot loop.
// Round 5: one warp per node; ALL of a node's row loads (up to 16 at a time)
// issued in a single predicated burst -> MLP == degree for 97% of nodes.

#define NMAX  100000
#define DF    64
#define DF2   (DF / 2)
#define DF4   (DF / 4)
#define EMAX  1000000
#define KITER 10
#define SCAN_T 1024
#define BURST 16

__device__ float g_a[NMAX * DF];     // ping
__device__ float g_b[NMAX * DF];     // pong
__device__ float g_norm[NMAX];
__device__ int   g_deg[NMAX];
__device__ int   g_rowptr[NMAX + 1];
__device__ int   g_cursor[NMAX];
__device__ int   g_srcs[EMAX];       // src ids sorted by dst bucket

// ---------------------------------------------------------------- build ----

__global__ void k_zero(int n) {
    int i = blockIdx.x * blockDim.x + threadIdx.x;
    if (i < n) { g_deg[i] = 0; g_cursor[i] = 0; }
}

__global__ void k_deg(const int* __restrict__ dst, int e) {
    int i = blockIdx.x * blockDim.x + threadIdx.x;
    if (i < e) atomicAdd(&g_deg[dst[i]], 1);
}

// Single-block exclusive scan of g_deg -> g_rowptr; also norm = deg^{-1/2}.
__global__ void k_scan(int n, int e) {
    __shared__ int sums[SCAN_T];
    int t = threadIdx.x;
    int chunk = (n + SCAN_T - 1) / SCAN_T;
    int start = t * chunk;
    int end   = min(start + chunk, n);
    int s = 0;
    for (int i = start; i < end; ++i) s += g_deg[i];
    sums[t] = s;
    __syncthreads();
    for (int off = 1; off < SCAN_T; off <<= 1) {
        int x = (t >= off) ? sums[t - off] : 0;
        __syncthreads();
        sums[t] += x;
        __syncthreads();
    }
    int run = sums[t] - s;  // exclusive prefix of my chunk
    for (int i = start; i < end; ++i) {
        int d = g_deg[i];
        g_rowptr[i] = run;
        g_norm[i]   = rsqrtf(fmaxf((float)d, 1.0f));
        run += d;
    }
    if (t == 0) g_rowptr[n] = e;
}

__global__ void k_fill(const int* __restrict__ src,
                       const int* __restrict__ dst, int e) {
    int i = blockIdx.x * blockDim.x + threadIdx.x;
    if (i < e) {
        int d = dst[i];
        int pos = g_rowptr[d] + atomicAdd(&g_cursor[d], 1);
        g_srcs[pos] = src[i];
    }
}

// g_0 = norm ⊙ feat  (into g_a)
__global__ void k_init(const float* __restrict__ feat, int n) {
    int i = blockIdx.x * blockDim.x + threadIdx.x;
    if (i < n * DF4) {
        int row = i >> 4;
        float nm = g_norm[row];
        float4 f = reinterpret_cast<const float4*>(feat)[i];
        f.x *= nm; f.y *= nm; f.z *= nm; f.w *= nm;
        reinterpret_cast<float4*>(g_a)[i] = f;
    }
}

// ----------------------------------------------------------------- loop ----

// One warp per destination node; lane owns 2 columns (float2). Src ids come
// from uniform broadcast loads. Row loads are issued in ONE predicated
// 16-wide burst per trip, so the memory system sees MLP == min(deg,16).
__global__ void __launch_bounds__(256) k_prop(const float* __restrict__ feat,
                       float* __restrict__ out,
                       int n, int flip, int last) {
    int gt   = blockIdx.x * blockDim.x + threadIdx.x;
    int v    = gt >> 5;
    int lane = gt & 31;
    if (v >= n) return;

    const float2* gin  = reinterpret_cast<const float2*>(flip ? g_b : g_a);
    float2*       gout = reinterpret_cast<float2*>(flip ? g_a : g_b);

    int idx = g_rowptr[v];
    int end = g_rowptr[v + 1];

    float ax = 0.f, ay = 0.f;

    while (idx < end) {
        int cnt = end - idx;            // >= 1
        int s[BURST];
        #pragma unroll
        for (int k = 0; k < BURST; ++k)
            s[k] = (k < cnt) ? __ldg(&g_srcs[idx + k]) : -1;
        float2 vv[BURST];
        #pragma unroll
        for (int k = 0; k < BURST; ++k)
            vv[k] = (k < cnt) ? gin[s[k] * DF2 + lane] : make_float2(0.f, 0.f);
        #pragma unroll
        for (int k = 0; k < BURST; ++k) { ax += vv[k].x; ay += vv[k].y; }
        idx += BURST;
    }

    float nm = g_norm[v];
    float2 f = reinterpret_cast<const float2*>(feat)[v * DF2 + lane];
    float2 o;
    if (!last) {
        float c1 = 0.9f * nm * nm;
        float c2 = 0.1f * nm;
        o.x = c1 * ax + c2 * f.x;
        o.y = c1 * ay + c2 * f.y;
        gout[v * DF2 + lane] = o;
    } else {
        float c1 = 0.9f * nm;
        o.x = c1 * ax + 0.1f * f.x;
        o.y = c1 * ay + 0.1f * f.y;
        reinterpret_cast<float2*>(out)[v * DF2 + lane] = o;
    }
}

// ---------------------------------------------------------------- launch ----

extern "C" void kernel_launch(void* const* d_in, const int* in_sizes, int n_in,
                              void* d_out, int out_size) {
    const float* feat = (const float*)d_in[0];
    const int*   src  = (const int*)d_in[1];
    const int*   dst  = (const int*)d_in[2];
    float*       out  = (float*)d_out;

    int n = in_sizes[0] / DF;   // 100000
    int e = in_sizes[1];        // 1000000

    const int T = 256;
    int blk_n   = (n + T - 1) / T;
    int blk_e   = (e + T - 1) / T;
    int blk_nd4 = (n * DF4 + T - 1) / T;
    int blk_p   = (n * 32 + T - 1) / T;     // warp per node

    // CSR build (per call; graph-capturable, no allocs)
    k_zero<<<blk_n, T>>>(n);
    k_deg<<<blk_e, T>>>(dst, e);
    k_scan<<<1, SCAN_T>>>(n, e);
    k_fill<<<blk_e, T>>>(src, dst, e);
    k_init<<<blk_nd4, T>>>(feat, n);

    // Propagation: ping-pong g_a <-> g_b, final iter writes d_out.
    for (int t = 0; t < KITER; ++t) {
        int flip = t & 1;
        int last = (t == KITER - 1);
        k_prop<<<blk_p, T>>>(feat, out, n, flip, last);
    }
}

// round 6
// speedup vs baseline: 1.9852x; 1.9852x over previous
#include <cuda_runtime.h>

// APPNP, K=10:  g_{t+1} = 0.9*norm^2 * (sum_{(s->v) in E} g_t[s]) + 0.1*norm*feat0
// where g = norm ⊙ h. Final: h = 0.9*norm*agg + 0.1*feat0.
//
// CSR gather (edges counting-sorted by dst), zero atomics in the hot loop.
// Round 6: (a) fully parallel 3-stage rowptr scan (old single-block scan ran
// on one SM); (b) gather loop = unpredicated burst-8 main loop + one
// predicated burst-8 tail, so every row load is inside an MLP window.

#define NMAX  100000
#define DF    64
#define DF2   (DF / 2)
#define DF4   (DF / 4)
#define EMAX  1000000
#define KITER 10
#define TILE  256
#define NTILE ((NMAX + TILE - 1) / TILE)   // 391

__device__ float g_a[NMAX * DF];     // ping
__device__ float g_b[NMAX * DF];     // pong
__device__ float g_norm[NMAX];
__device__ int   g_deg[NMAX];
__device__ int   g_rowptr[NMAX + 1];
__device__ int   g_cursor[NMAX];
__device__ int   g_srcs[EMAX];       // src ids sorted by dst bucket
__device__ int   g_part[NTILE];      // per-tile degree sums -> exclusive prefix

// ---------------------------------------------------------------- build ----

__global__ void k_zero(int n) {
    int i = blockIdx.x * blockDim.x + threadIdx.x;
    if (i < n) { g_deg[i] = 0; g_cursor[i] = 0; }
}

__global__ void k_deg(const int* __restrict__ dst, int e) {
    int i = blockIdx.x * blockDim.x + threadIdx.x;
    if (i < e) atomicAdd(&g_deg[dst[i]], 1);
}

// Stage 1: per-tile (256 nodes) degree sums.
__global__ void k_scan_part(int n) {
    __shared__ int sh[TILE];
    int t = threadIdx.x;
    int i = blockIdx.x * TILE + t;
    sh[t] = (i < n) ? g_deg[i] : 0;
    __syncthreads();
    for (int off = TILE >> 1; off > 0; off >>= 1) {
        if (t < off) sh[t] += sh[t + off];
        __syncthreads();
    }
    if (t == 0) g_part[blockIdx.x] = sh[0];
}

// Stage 2: single block, exclusive scan of the 391 tile sums.
__global__ void k_scan_top(int nb) {
    __shared__ int sh[512];
    int t = threadIdx.x;
    int v = (t < nb) ? g_part[t] : 0;
    sh[t] = v;
    __syncthreads();
    for (int off = 1; off < 512; off <<= 1) {
        int x = (t >= off) ? sh[t - off] : 0;
        __syncthreads();
        sh[t] += x;
        __syncthreads();
    }
    if (t < nb) g_part[t] = sh[t] - v;   // exclusive
}

// Stage 3: per-tile local exclusive scan + tile offset -> rowptr; also norm.
__global__ void k_scan_fin(int n, int e) {
    __shared__ int sh[TILE];
    int t = threadIdx.x;
    int i = blockIdx.x * TILE + t;
    int d = (i < n) ? g_deg[i] : 0;
    sh[t] = d;
    __syncthreads();
    for (int off = 1; off < TILE; off <<= 1) {
        int x = (t >= off) ? sh[t - off] : 0;
        __syncthreads();
        sh[t] += x;
        __syncthreads();
    }
    if (i < n) {
        g_rowptr[i] = sh[t] - d + g_part[blockIdx.x];
        g_norm[i]   = rsqrtf(fmaxf((float)d, 1.0f));
    }
    if (i == n) g_rowptr[n] = e;
}

__global__ void k_fill(const int* __restrict__ src,
                       const int* __restrict__ dst, int e) {
    int i = blockIdx.x * blockDim.x + threadIdx.x;
    if (i < e) {
        int d = dst[i];
        int pos = g_rowptr[d] + atomicAdd(&g_cursor[d], 1);
        g_srcs[pos] = src[i];
    }
}

// g_0 = norm ⊙ feat  (into g_a)
__global__ void k_init(const float* __restrict__ feat, int n) {
    int i = blockIdx.x * blockDim.x + threadIdx.x;
    if (i < n * DF4) {
        int row = i >> 4;
        float nm = g_norm[row];
        float4 f = reinterpret_cast<const float4*>(feat)[i];
        f.x *= nm; f.y *= nm; f.z *= nm; f.w *= nm;
        reinterpret_cast<float4*>(g_a)[i] = f;
    }
}

// ----------------------------------------------------------------- loop ----

// One warp per destination node; lane owns 2 columns (float2). Src ids via
// uniform broadcast loads. Main loop: unpredicated bursts of 8 (MLP=8).
// Tail (<8 edges): one predicated 8-wide burst.
__global__ void __launch_bounds__(256) k_prop(const float* __restrict__ feat,
                       float* __restrict__ out,
                       int n, int flip, int last) {
    int gt   = blockIdx.x * blockDim.x + threadIdx.x;
    int v    = gt >> 5;
    int lane = gt & 31;
    if (v >= n) return;

    const float2* gin  = reinterpret_cast<const float2*>(flip ? g_b : g_a);
    float2*       gout = reinterpret_cast<float2*>(flip ? g_a : g_b);

    int idx = g_rowptr[v];
    int end = g_rowptr[v + 1];

    float ax = 0.f, ay = 0.f;

    // full bursts of 8 (no predication)
    for (; idx + 8 <= end; idx += 8) {
        int s[8];
        #pragma unroll
        for (int k = 0; k < 8; ++k) s[k] = __ldg(&g_srcs[idx + k]);
        float2 vv[8];
        #pragma unroll
        for (int k = 0; k < 8; ++k) vv[k] = gin[s[k] * DF2 + lane];
        #pragma unroll
        for (int k = 0; k < 8; ++k) { ax += vv[k].x; ay += vv[k].y; }
    }
    // predicated tail burst (0 < cnt < 8), executed at most once
    int cnt = end - idx;
    if (cnt > 0) {
        int s[8];
        #pragma unroll
        for (int k = 0; k < 8; ++k)
            s[k] = (k < cnt) ? __ldg(&g_srcs[idx + k]) : 0;
        float2 vv[8];
        #pragma unroll
        for (int k = 0; k < 8; ++k)
            vv[k] = (k < cnt) ? gin[s[k] * DF2 + lane] : make_float2(0.f, 0.f);
        #pragma unroll
        for (int k = 0; k < 8; ++k) { ax += vv[k].x; ay += vv[k].y; }
    }

    float nm = g_norm[v];
    float2 f = reinterpret_cast<const float2*>(feat)[v * DF2 + lane];
    float2 o;
    if (!last) {
        float c1 = 0.9f * nm * nm;
        float c2 = 0.1f * nm;
        o.x = c1 * ax + c2 * f.x;
        o.y = c1 * ay + c2 * f.y;
        gout[v * DF2 + lane] = o;
    } else {
        float c1 = 0.9f * nm;
        o.x = c1 * ax + 0.1f * f.x;
        o.y = c1 * ay + 0.1f * f.y;
        reinterpret_cast<float2*>(out)[v * DF2 + lane] = o;
    }
}

// ---------------------------------------------------------------- launch ----

extern "C" void kernel_launch(void* const* d_in, const int* in_sizes, int n_in,
                              void* d_out, int out_size) {
    const float* feat = (const float*)d_in[0];
    const int*   src  = (const int*)d_in[1];
    const int*   dst  = (const int*)d_in[2];
    float*       out  = (float*)d_out;

    int n = in_sizes[0] / DF;   // 100000
    int e = in_sizes[1];        // 1000000

    const int T = 256;
    int blk_n   = (n + T - 1) / T;
    int blk_e   = (e + T - 1) / T;
    int blk_nd4 = (n * DF4 + T - 1) / T;
    int blk_p   = (n * 32 + T - 1) / T;     // warp per node
    int nb      = (n + TILE - 1) / TILE;    // 391

    // CSR build (per call; graph-capturable, no allocs)
    k_zero<<<blk_n, T>>>(n);
    k_deg<<<blk_e, T>>>(dst, e);
    k_scan_part<<<nb, TILE>>>(n);
    k_scan_top<<<1, 512>>>(nb);
    k_scan_fin<<<nb + 1, TILE>>>(n, e);     // +1 block so i==n thread exists
    k_fill<<<blk_e, T>>>(src, dst, e);
    k_init<<<blk_nd4, T>>>(feat, n);

    // Propagation: ping-pong g_a <-> g_b, final iter writes d_out.
    for (int t = 0; t < KITER; ++t) {
        int flip = t & 1;
        int last = (t == KITER - 1);
        k_prop<<<blk_p, T>>>(feat, out, n, flip, last);
    }
}

// round 7
// speedup vs baseline: 2.1010x; 1.0583x over previous
#include <cuda_runtime.h>
#include <cuda_fp16.h>

// APPNP, K=10:  g_{t+1} = 0.9*norm^2 * (sum_{(s->v) in E} g_t[s]) + 0.1*norm*feat0
// where g = norm ⊙ h. Final: h = 0.9*norm*agg + 0.1*feat0 (fp32).
//
// CSR gather (edges counting-sorted by dst), zero atomics in the hot loop.
// Round 7: ping-pong state stored as fp16 (rows 128B instead of 256B) — the
// loop was measured AT the L2 byte roofline, so halving gather bytes halves
// iteration time. Accumulation stays fp32; feat anchor and output stay fp32.

#define NMAX  100000
#define DF    64
#define DF2   (DF / 2)
#define DF4   (DF / 4)
#define EMAX  1000000
#define KITER 10
#define TILE  256
#define NTILE ((NMAX + TILE - 1) / TILE)   // 391

__device__ __half2 g_a[NMAX * DF2];  // ping (fp16 state)
__device__ __half2 g_b[NMAX * DF2];  // pong
__device__ float   g_norm[NMAX];
__device__ int     g_deg[NMAX];
__device__ int     g_rowptr[NMAX + 1];
__device__ int     g_cursor[NMAX];
__device__ int     g_srcs[EMAX];     // src ids sorted by dst bucket
__device__ int     g_part[NTILE];    // per-tile degree sums -> exclusive prefix

// ---------------------------------------------------------------- build ----

__global__ void k_zero(int n) {
    int i = blockIdx.x * blockDim.x + threadIdx.x;
    if (i < n) { g_deg[i] = 0; g_cursor[i] = 0; }
}

__global__ void k_deg(const int* __restrict__ dst, int e) {
    int i = blockIdx.x * blockDim.x + threadIdx.x;
    if (i < e) atomicAdd(&g_deg[dst[i]], 1);
}

// Stage 1: per-tile (256 nodes) degree sums.
__global__ void k_scan_part(int n) {
    __shared__ int sh[TILE];
    int t = threadIdx.x;
    int i = blockIdx.x * TILE + t;
    sh[t] = (i < n) ? g_deg[i] : 0;
    __syncthreads();
    for (int off = TILE >> 1; off > 0; off >>= 1) {
        if (t < off) sh[t] += sh[t + off];
        __syncthreads();
    }
    if (t == 0) g_part[blockIdx.x] = sh[0];
}

// Stage 2: single block, exclusive scan of the 391 tile sums.
__global__ void k_scan_top(int nb) {
    __shared__ int sh[512];
    int t = threadIdx.x;
    int v = (t < nb) ? g_part[t] : 0;
    sh[t] = v;
    __syncthreads();
    for (int off = 1; off < 512; off <<= 1) {
        int x = (t >= off) ? sh[t - off] : 0;
        __syncthreads();
        sh[t] += x;
        __syncthreads();
    }
    if (t < nb) g_part[t] = sh[t] - v;   // exclusive
}

// Stage 3: per-tile local exclusive scan + tile offset -> rowptr; also norm.
__global__ void k_scan_fin(int n, int e) {
    __shared__ int sh[TILE];
    int t = threadIdx.x;
    int i = blockIdx.x * TILE + t;
    int d = (i < n) ? g_deg[i] : 0;
    sh[t] = d;
    __syncthreads();
    for (int off = 1; off < TILE; off <<= 1) {
        int x = (t >= off) ? sh[t - off] : 0;
        __syncthreads();
        sh[t] += x;
        __syncthreads();
    }
    if (i < n) {
        g_rowptr[i] = sh[t] - d + g_part[blockIdx.x];
        g_norm[i]   = rsqrtf(fmaxf((float)d, 1.0f));
    }
    if (i == n) g_rowptr[n] = e;
}

__global__ void k_fill(const int* __restrict__ src,
                       const int* __restrict__ dst, int e) {
    int i = blockIdx.x * blockDim.x + threadIdx.x;
    if (i < e) {
        int d = dst[i];
        int pos = g_rowptr[d] + atomicAdd(&g_cursor[d], 1);
        g_srcs[pos] = src[i];
    }
}

// g_0 = norm ⊙ feat  (into g_a, fp16)
__global__ void k_init(const float* __restrict__ feat, int n) {
    int i = blockIdx.x * blockDim.x + threadIdx.x;
    if (i < n * DF2) {
        int row = i >> 5;
        float nm = g_norm[row];
        float2 f = reinterpret_cast<const float2*>(feat)[i];
        g_a[i] = __floats2half2_rn(nm * f.x, nm * f.y);
    }
}

// ----------------------------------------------------------------- loop ----

// One warp per destination node; lane owns 2 columns (one __half2, 4B). Src
// ids via uniform broadcast loads. Main loop: unpredicated bursts of 8
// (MLP=8). Tail (<8 edges): one predicated 8-wide burst. Accumulate fp32.
__global__ void __launch_bounds__(256) k_prop(const float* __restrict__ feat,
                       float* __restrict__ out,
                       int n, int flip, int last) {
    int gt   = blockIdx.x * blockDim.x + threadIdx.x;
    int v    = gt >> 5;
    int lane = gt & 31;
    if (v >= n) return;

    const __half2* gin  = flip ? g_b : g_a;
    __half2*       gout = flip ? g_a : g_b;

    int idx = g_rowptr[v];
    int end = g_rowptr[v + 1];

    float ax = 0.f, ay = 0.f;

    // full bursts of 8 (no predication)
    for (; idx + 8 <= end; idx += 8) {
        int s[8];
        #pragma unroll
        for (int k = 0; k < 8; ++k) s[k] = __ldg(&g_srcs[idx + k]);
        __half2 vv[8];
        #pragma unroll
        for (int k = 0; k < 8; ++k) vv[k] = gin[s[k] * DF2 + lane];
        #pragma unroll
        for (int k = 0; k < 8; ++k) {
            float2 w = __half22float2(vv[k]);
            ax += w.x; ay += w.y;
        }
    }
    // predicated tail burst (0 < cnt < 8), executed at most once
    int cnt = end - idx;
    if (cnt > 0) {
        int s[8];
        #pragma unroll
        for (int k = 0; k < 8; ++k)
            s[k] = (k < cnt) ? __ldg(&g_srcs[idx + k]) : 0;
        __half2 vv[8];
        #pragma unroll
        for (int k = 0; k < 8; ++k)
            vv[k] = (k < cnt) ? gin[s[k] * DF2 + lane]
                              : __floats2half2_rn(0.f, 0.f);
        #pragma unroll
        for (int k = 0; k < 8; ++k) {
            float2 w = __half22float2(vv[k]);
            ax += w.x; ay += w.y;
        }
    }

    float nm = g_norm[v];
    float2 f = reinterpret_cast<const float2*>(feat)[v * DF2 + lane];
    if (!last) {
        float c1 = 0.9f * nm * nm;
        float c2 = 0.1f * nm;
        gout[v * DF2 + lane] =
            __floats2half2_rn(c1 * ax + c2 * f.x, c1 * ay + c2 * f.y);
    } else {
        float c1 = 0.9f * nm;
        float2 o;
        o.x = c1 * ax + 0.1f * f.x;
        o.y = c1 * ay + 0.1f * f.y;
        reinterpret_cast<float2*>(out)[v * DF2 + lane] = o;
    }
}

// ---------------------------------------------------------------- launch ----

extern "C" void kernel_launch(void* const* d_in, const int* in_sizes, int n_in,
                              void* d_out, int out_size) {
    const float* feat = (const float*)d_in[0];
    const int*   src  = (const int*)d_in[1];
    const int*   dst  = (const int*)d_in[2];
    float*       out  = (float*)d_out;

    int n = in_sizes[0] / DF;   // 100000
    int e = in_sizes[1];        // 1000000

    const int T = 256;
    int blk_n   = (n + T - 1) / T;
    int blk_e   = (e + T - 1) / T;
    int blk_nd2 = (n * DF2 + T - 1) / T;
    int blk_p   = (n * 32 + T - 1) / T;     // warp per node
    int nb      = (n + TILE - 1) / TILE;    // 391

    // CSR build (per call; graph-capturable, no allocs)
    k_zero<<<blk_n, T>>>(n);
    k_deg<<<blk_e, T>>>(dst, e);
    k_scan_part<<<nb, TILE>>>(n);
    k_scan_top<<<1, 512>>>(nb);
    k_scan_fin<<<nb + 1, TILE>>>(n, e);     // +1 block so i==n thread exists
    k_fill<<<blk_e, T>>>(src, dst, e);
    k_init<<<blk_nd2, T>>>(feat, n);

    // Propagation: ping-pong g_a <-> g_b, final iter writes d_out (fp32).
    for (int t = 0; t < KITER; ++t) {
        int flip = t & 1;
        int last = (t == KITER - 1);
        k_prop<<<blk_p, T>>>(feat, out, n, flip, last);
    }
}

// round 8
// speedup vs baseline: 2.1046x; 1.0017x over previous
#include <cuda_runtime.h>
#include <cuda_fp16.h>

// APPNP, K=10. State g = norm ⊙ h kept in fp16 (row = 64 halves = 128B).
//   g_{t+1} = 0.9*norm^2 * (sum_{(s->v)} g_t[s]) + anchor,  anchor = 0.1*norm*feat (fp16)
// Final: h = 0.9*norm*agg + 0.1*feat  (fp32 feat, fp32 out).
//
// Round 8: SIMT-4 gather — one warp LDG.128 fetches FOUR 128B edge rows
// (8 lanes per row); per-lane fp32 partials, xor-shuffle fold at the end.
// CSR segments padded to a multiple of 4 with a dummy zero row, so the hot
// loop has zero predication. Cuts memory instructions per node ~2.5x
// (the loop was measured LSU-issue-bound, not byte-bound).

#define NMAX  100000
#define DF    64
#define DF2   (DF / 2)
#define EMAX  1000000
#define EPAD  (EMAX + 4 * NMAX + 32)
#define KITER 10
#define TILE  256
#define NTILE ((NMAX + TILE - 1) / TILE)   // 391

// State rows as uint4 (8 uint4 = 128B per row). Row NMAX-index `n` is the
// zeroed dummy row targeted by pad entries.
__device__ uint4 g_a[(NMAX + 1) * 8];
__device__ uint4 g_b[(NMAX + 1) * 8];
__device__ uint4 g_anchor[(NMAX + 1) * 8];  // 0.1*norm*feat in fp16
__device__ float g_norm[NMAX];
__device__ int   g_deg[NMAX];
__device__ int   g_rowptr[NMAX + 1];        // padded-degree prefix
__device__ int   g_cursor[NMAX];
__device__ int   g_srcs[EPAD];
__device__ int   g_part[NTILE];

// ---------------------------------------------------------------- build ----

__global__ void k_zero(int n) {
    int i = blockIdx.x * blockDim.x + threadIdx.x;
    if (i < n) { g_deg[i] = 0; g_cursor[i] = 0; }
}

__global__ void k_deg(const int* __restrict__ dst, int e) {
    int i = blockIdx.x * blockDim.x + threadIdx.x;
    if (i < e) atomicAdd(&g_deg[dst[i]], 1);
}

// Stage 1: per-tile sums of PADDED degrees.
__global__ void k_scan_part(int n) {
    __shared__ int sh[TILE];
    int t = threadIdx.x;
    int i = blockIdx.x * TILE + t;
    int d = (i < n) ? g_deg[i] : 0;
    sh[t] = (d + 3) & ~3;
    __syncthreads();
    for (int off = TILE >> 1; off > 0; off >>= 1) {
        if (t < off) sh[t] += sh[t + off];
        __syncthreads();
    }
    if (t == 0) g_part[blockIdx.x] = sh[0];
}

// Stage 2: single block, exclusive scan of tile sums.
__global__ void k_scan_top(int nb) {
    __shared__ int sh[512];
    int t = threadIdx.x;
    int v = (t < nb) ? g_part[t] : 0;
    sh[t] = v;
    __syncthreads();
    for (int off = 1; off < 512; off <<= 1) {
        int x = (t >= off) ? sh[t - off] : 0;
        __syncthreads();
        sh[t] += x;
        __syncthreads();
    }
    if (t < nb) g_part[t] = sh[t] - v;
}

// Stage 3: per-tile scan of padded degrees -> rowptr; also norm.
__global__ void k_scan_fin(int n) {
    __shared__ int sh[TILE];
    int t = threadIdx.x;
    int i = blockIdx.x * TILE + t;
    int d    = (i < n) ? g_deg[i] : 0;
    int dpad = (d + 3) & ~3;
    sh[t] = dpad;
    __syncthreads();
    for (int off = 1; off < TILE; off <<= 1) {
        int x = (t >= off) ? sh[t - off] : 0;
        __syncthreads();
        sh[t] += x;
        __syncthreads();
    }
    if (i < n) {
        g_rowptr[i] = sh[t] - dpad + g_part[blockIdx.x];
        g_norm[i]   = rsqrtf(fmaxf((float)d, 1.0f));
        if (i == n - 1) g_rowptr[n] = sh[t] + g_part[blockIdx.x];
    }
}

__global__ void k_fill(const int* __restrict__ src,
                       const int* __restrict__ dst, int e) {
    int i = blockIdx.x * blockDim.x + threadIdx.x;
    if (i < e) {
        int d = dst[i];
        int pos = g_rowptr[d] + atomicAdd(&g_cursor[d], 1);
        g_srcs[pos] = src[i];
    }
}

// Fill pad slots [rowptr+deg, rowptr+dpad) with the dummy row index n.
__global__ void k_pad(int n) {
    int i = blockIdx.x * blockDim.x + threadIdx.x;
    if (i < n) {
        int s  = g_rowptr[i] + g_deg[i];
        int e2 = g_rowptr[i + 1];
        for (int j = s; j < e2; ++j) g_srcs[j] = n;
    }
}

// g_a = fp16(norm*feat), anchor = fp16(0.1*norm*feat); zero dummy row (= row n)
// of g_a, g_b, anchor.
__global__ void k_init(const float* __restrict__ feat, int n) {
    int i = blockIdx.x * blockDim.x + threadIdx.x;   // half2 index
    int tot = (n + 1) * DF2;
    if (i >= tot) return;
    __half2* pa = reinterpret_cast<__half2*>(g_a);
    __half2* pb = reinterpret_cast<__half2*>(g_b);
    __half2* pn = reinterpret_cast<__half2*>(g_anchor);
    int row = i >> 5;
    if (row < n) {
        float nm = g_norm[row];
        float2 f = reinterpret_cast<const float2*>(feat)[i];
        pa[i] = __floats2half2_rn(nm * f.x, nm * f.y);
        pn[i] = __floats2half2_rn(0.1f * nm * f.x, 0.1f * nm * f.y);
    } else {
        __half2 z = __floats2half2_rn(0.f, 0.f);
        pa[i] = z; pb[i] = z; pn[i] = z;
    }
}

// ----------------------------------------------------------------- loop ----

__device__ __forceinline__ void acc_row(const uint4& r, float* acc) {
    const __half2* h = reinterpret_cast<const __half2*>(&r);
    #pragma unroll
    for (int j = 0; j < 4; ++j) {
        float2 w = __half22float2(h[j]);
        acc[2 * j]     += w.x;
        acc[2 * j + 1] += w.y;
    }
}

// One warp per node. Each LDG.128 fetches 4 edge rows (8 lanes/row).
// Lane's slot = lane>>3; lane's column-octet = (lane&7)*8 float columns.
__global__ void __launch_bounds__(256) k_prop(const float* __restrict__ feat,
                       float* __restrict__ out,
                       int n, int flip, int last) {
    int gt   = blockIdx.x * blockDim.x + threadIdx.x;
    int v    = gt >> 5;
    int lane = gt & 31;
    if (v >= n) return;

    const uint4* gin  = flip ? g_b : g_a;
    uint4*       gout = flip ? g_a : g_b;

    int idx = __ldg(&g_rowptr[v]);
    int end = __ldg(&g_rowptr[v + 1]);   // padded: (end-idx) % 4 == 0

    int slot = lane >> 3;
    int oct  = lane & 7;

    float acc[8];
    #pragma unroll
    for (int j = 0; j < 8; ++j) acc[j] = 0.f;

    // 8 padded edges per trip: 2 id LDGs + 2 row LDG.128s, no predication.
    for (; idx + 8 <= end; idx += 8) {
        int s0 = __ldg(&g_srcs[idx + slot]);
        int s1 = __ldg(&g_srcs[idx + 4 + slot]);
        uint4 r0 = gin[s0 * 8 + oct];
        uint4 r1 = gin[s1 * 8 + oct];
        acc_row(r0, acc);
        acc_row(r1, acc);
    }
    // optional trailing 4
    if (idx < end) {
        int s0 = __ldg(&g_srcs[idx + slot]);
        uint4 r0 = gin[s0 * 8 + oct];
        acc_row(r0, acc);
    }

    // fold the 4 edge-slots (lane bits 3 and 4)
    #pragma unroll
    for (int j = 0; j < 8; ++j) {
        acc[j] += __shfl_xor_sync(0xffffffff, acc[j], 8);
        acc[j] += __shfl_xor_sync(0xffffffff, acc[j], 16);
    }

    float nm = __ldg(&g_norm[v]);

    if (!last) {
        if (lane < 8) {
            float c1 = 0.9f * nm * nm;
            uint4 an = g_anchor[v * 8 + oct];
            const __half2* ah = reinterpret_cast<const __half2*>(&an);
            uint4 o;
            __half2* oh = reinterpret_cast<__half2*>(&o);
            #pragma unroll
            for (int j = 0; j < 4; ++j) {
                float2 a2 = __half22float2(ah[j]);
                oh[j] = __floats2half2_rn(c1 * acc[2 * j]     + a2.x,
                                          c1 * acc[2 * j + 1] + a2.y);
            }
            gout[v * 8 + oct] = o;
        }
    } else {
        if (lane < 8) {
            float c1 = 0.9f * nm;
            const float4* fr = reinterpret_cast<const float4*>(feat + v * DF);
            float4*       orow = reinterpret_cast<float4*>(out + v * DF);
            float4 f0 = fr[oct * 2];
            float4 f1 = fr[oct * 2 + 1];
            float4 o0, o1;
            o0.x = c1 * acc[0] + 0.1f * f0.x;
            o0.y = c1 * acc[1] + 0.1f * f0.y;
            o0.z = c1 * acc[2] + 0.1f * f0.z;
            o0.w = c1 * acc[3] + 0.1f * f0.w;
            o1.x = c1 * acc[4] + 0.1f * f1.x;
            o1.y = c1 * acc[5] + 0.1f * f1.y;
            o1.z = c1 * acc[6] + 0.1f * f1.z;
            o1.w = c1 * acc[7] + 0.1f * f1.w;
            orow[oct * 2]     = o0;
            orow[oct * 2 + 1] = o1;
        }
    }
}

// ---------------------------------------------------------------- launch ----

extern "C" void kernel_launch(void* const* d_in, const int* in_sizes, int n_in,
                              void* d_out, int out_size) {
    const float* feat = (const float*)d_in[0];
    const int*   src  = (const int*)d_in[1];
    const int*   dst  = (const int*)d_in[2];
    float*       out  = (float*)d_out;

    int n = in_sizes[0] / DF;   // 100000
    int e = in_sizes[1];        // 1000000

    const int T = 256;
    int blk_n   = (n + T - 1) / T;
    int blk_e   = (e + T - 1) / T;
    int blk_i   = ((n + 1) * DF2 + T - 1) / T;
    int blk_p   = (n * 32 + T - 1) / T;     // warp per node
    int nb      = (n + TILE - 1) / TILE;

    // CSR build with 4-padded segments
    k_zero<<<blk_n, T>>>(n);
    k_deg<<<blk_e, T>>>(dst, e);
    k_scan_part<<<nb, TILE>>>(n);
    k_scan_top<<<1, 512>>>(nb);
    k_scan_fin<<<nb, TILE>>>(n);
    k_fill<<<blk_e, T>>>(src, dst, e);
    k_pad<<<blk_n, T>>>(n);
    k_init<<<blk_i, T>>>(feat, n);

    // Propagation: ping-pong g_a <-> g_b, final iter writes d_out (fp32).
    for (int t = 0; t < KITER; ++t) {
        int flip = t & 1;
        int last = (t == KITER - 1);
        k_prop<<<blk_p, T>>>(feat, out, n, flip, last);
    }
}